// round 16
// baseline (speedup 1.0000x reference)
#include <cuda_runtime.h>
#include <cuda_fp16.h>
#include <cstdint>

#define D    256
#define BM   64            // edges per CTA
#define KC   16            // K chunk (one k-step per chunk)
#define NCHUNK 16
#define NT   256

// ---- smem byte offsets ----
#define AHI_OFF   0        // [64 rows][512B] swizzled fp16-hi   32KB
#define ALO_OFF   32768    // fp16-lo                            32KB
#define BBUF_OFF  65536    // 2 bufs x 16KB (hi 8KB + lo 8KB)    32KB
#define EIDX_OFF  98304    // 128 ints
#define B1S_OFF   (EIDX_OFF + 512)
#define W2S_OFF   (B1S_OFF + 1024)
#define RED_OFF   (W2S_OFF + 1024)   // 4 x 64 floats
#define SMEM_TOTAL (RED_OFF + 1024)  // 101888 B (~99.5KB) -> 2 CTAs/SM

// W1^T fp16 hi/lo, final swizzled tile layout, chunked by KC=16:
// chunk c: 16KB = [hi 8KB][lo 8KB]; within blob:
//   byte = kk*512 + ((nch ^ (kk&7))<<4) + (n&7)*2,  kk=k&15, nch=(n>>3)&31
__device__ __align__(16) char g_Bprep[262144];

__device__ __forceinline__ uint32_t smem_u32(const void* p) {
    uint32_t a;
    asm("{ .reg .u64 t; cvta.to.shared.u64 t, %1; cvt.u32.u64 %0, t; }"
        : "=r"(a) : "l"(p));
    return a;
}
__device__ __forceinline__ void cp16(uint32_t dst, const void* src) {
    asm volatile("{ .reg .u64 g; cvta.to.global.u64 g, %1;"
                 " cp.async.cg.shared.global [%0], [g], 16; }"
                 :: "r"(dst), "l"(src) : "memory");
}
__device__ __forceinline__ void ldsm4(uint32_t* r, uint32_t a) {
    asm volatile("ldmatrix.sync.aligned.m8n8.x4.shared.b16 {%0,%1,%2,%3}, [%4];"
                 : "=r"(r[0]), "=r"(r[1]), "=r"(r[2]), "=r"(r[3]) : "r"(a));
}
__device__ __forceinline__ void ldsm4t(uint32_t* r, uint32_t a) {
    asm volatile("ldmatrix.sync.aligned.m8n8.x4.trans.shared.b16 {%0,%1,%2,%3}, [%4];"
                 : "=r"(r[0]), "=r"(r[1]), "=r"(r[2]), "=r"(r[3]) : "r"(a));
}
__device__ __forceinline__ void mma16816(float* c, const uint32_t* a,
                                         uint32_t b0, uint32_t b1) {
    asm volatile("mma.sync.aligned.m16n8k16.row.col.f32.f16.f16.f32 "
                 "{%0,%1,%2,%3}, {%4,%5,%6,%7}, {%8,%9}, {%0,%1,%2,%3};"
                 : "+f"(c[0]), "+f"(c[1]), "+f"(c[2]), "+f"(c[3])
                 : "r"(a[0]), "r"(a[1]), "r"(a[2]), "r"(a[3]), "r"(b0), "r"(b1));
}

// ---- prep: W1 [k][n] f32 -> fp16 hi/lo, swizzled KC=16 tile blobs ----
__global__ void prep_w1(const float* __restrict__ W1) {
    int k = blockIdx.x;     // 0..255
    int n = threadIdx.x;    // 0..255
    float w = W1[k * D + n];
    __half hi = __float2half_rn(w);
    __half lo = __float2half_rn(w - __half2float(hi));
    int c = k >> 4, kk = k & 15;
    uint32_t base = (uint32_t)c * 16384u + (uint32_t)kk * 512u
                  + ((uint32_t)(((n >> 3) ^ (kk & 7)) & 31) << 4)
                  + (uint32_t)(n & 7) * 2u;
    *(__half*)(g_Bprep + base)        = hi;
    *(__half*)(g_Bprep + base + 8192) = lo;
}

__global__ __launch_bounds__(NT, 2)
void mlpdec_mma(const float* __restrict__ h,
                const void* __restrict__ edges_raw,
                const float* __restrict__ b1,
                const float* __restrict__ W2,
                const float* __restrict__ b2,
                float* __restrict__ out,
                int E)
{
    extern __shared__ char smem[];
    const uint32_t sb = smem_u32(smem);
    const int tid  = threadIdx.x;
    const int lane = tid & 31;
    const int wid  = tid >> 5;
    const int e0   = blockIdx.x * BM;

    int*   eidx = (int*)(smem + EIDX_OFF);
    float* b1s  = (float*)(smem + B1S_OFF);
    float* w2s  = (float*)(smem + W2S_OFF);
    float* red  = (float*)(smem + RED_OFF);

    // ---- kick off B chunk 0 copy immediately (16KB, 4x16B per thread) ----
    {
        const char* src = g_Bprep + tid * 16;
        uint32_t dst = sb + BBUF_OFF + tid * 16;
        #pragma unroll
        for (int i = 0; i < 4; i++) cp16(dst + i * 4096, src + i * 4096);
        asm volatile("cp.async.commit_group;" ::: "memory");
    }

    // ---- edge dtype probe (int64 of values <100000 has zero odd dwords) ----
    const int* w32 = (const int*)edges_raw;
    bool is64 = true;
    #pragma unroll
    for (int i = 0; i < 8; i++)
        if (w32[2 * i + 1] != 0) { is64 = false; break; }

    if (tid < BM) {
        long long e = (long long)e0 + tid;
        int s = 0, d = 0;
        if (e < E) {
            if (is64) {
                const long long* e64 = (const long long*)edges_raw;
                s = (int)e64[2 * e];
                d = (int)e64[2 * e + 1];
            } else {
                s = w32[2 * e];
                d = w32[2 * e + 1];
            }
        }
        eidx[tid]      = s;
        eidx[BM + tid] = d;
    }
    b1s[tid] = b1[tid];
    w2s[tid] = W2[tid];
    __syncthreads();

    // ---- produce A: hadamard -> fp16 hi/lo, swizzled ----
    {
        int row = tid & 63;
        int q   = tid >> 6;            // 0..3, covers k = q*64 .. q*64+63
        int s = eidx[row], d = eidx[BM + row];
        const float4* hs = (const float4*)(h + (size_t)s * D) + q * 16;
        const float4* hd = (const float4*)(h + (size_t)d * D) + q * 16;
        #pragma unroll
        for (int j = 0; j < 8; j++) {      // 8 chunks of 8 halfs
            float4 a0 = hs[2 * j], a1 = hs[2 * j + 1];
            float4 c0 = hd[2 * j], c1 = hd[2 * j + 1];
            float p[8] = { a0.x * c0.x, a0.y * c0.y, a0.z * c0.z, a0.w * c0.w,
                           a1.x * c1.x, a1.y * c1.y, a1.z * c1.z, a1.w * c1.w };
            union { __half hh[8]; uint4 v; } uhi, ulo;
            #pragma unroll
            for (int t = 0; t < 8; t++) {
                __half hv = __float2half_rn(p[t]);
                uhi.hh[t] = hv;
                ulo.hh[t] = __float2half_rn(p[t] - __half2float(hv));
            }
            int chunk = q * 8 + j;
            uint32_t byte = (uint32_t)row * 512u
                          + ((uint32_t)(chunk ^ (row & 7)) << 4);
            *(uint4*)(smem + AHI_OFF + byte) = uhi.v;
            *(uint4*)(smem + ALO_OFF + byte) = ulo.v;
        }
    }

    // ---- warp tiling: 2 M-groups (32 rows) x 4 N-groups (64 cols) ----
    const int mg = wid & 1;             // M group
    const int wn = wid >> 1;            // N group (0..3)
    float acc[2][4][2][4];              // [atile][ntile][nhalf][frag]
    #pragma unroll
    for (int t = 0; t < 2; t++)
        #pragma unroll
        for (int n = 0; n < 4; n++)
            #pragma unroll
            for (int hh = 0; hh < 2; hh++)
                #pragma unroll
                for (int f = 0; f < 4; f++) acc[t][n][hh][f] = 0.f;

    const uint32_t Ah = sb + AHI_OFF;
    const uint32_t Al = sb + ALO_OFF;
    const int arow0 = mg * 32 + (lane & 15);
    const int bkk   = (lane & 7) + ((lane >> 3) & 1) * 8;

    // ---- main loop: 16 K-chunks, double-buffered B via cp.async ----
    #pragma unroll 1
    for (int c = 0; c < NCHUNK; c++) {
        const int buf = c & 1;
        if (c < NCHUNK - 1) {
            const char* src = g_Bprep + (c + 1) * 16384 + tid * 16;
            uint32_t dst = sb + BBUF_OFF + ((c + 1) & 1) * 16384 + tid * 16;
            #pragma unroll
            for (int i = 0; i < 4; i++) cp16(dst + i * 4096, src + i * 4096);
            asm volatile("cp.async.commit_group;" ::: "memory");
            asm volatile("cp.async.wait_group 1;" ::: "memory");
        } else {
            asm volatile("cp.async.wait_group 0;" ::: "memory");
        }
        __syncthreads();

        // A fragments for this k-step (2 atiles, hi+lo)
        uint32_t ahf[2][4], alf[2][4];
        #pragma unroll
        for (int t = 0; t < 2; t++) {
            int arow = arow0 + t * 16;
            int achunk = c * 2 + (lane >> 4);
            uint32_t aaddr = (uint32_t)arow * 512u
                           + ((uint32_t)(achunk ^ (arow & 7)) << 4);
            ldsm4(ahf[t], Ah + aaddr);
            ldsm4(alf[t], Al + aaddr);
        }

        const uint32_t Bh = sb + BBUF_OFF + buf * 16384;
        const uint32_t Bl = Bh + 8192;
        const uint32_t brow = (uint32_t)bkk * 512u;

        #pragma unroll
        for (int nt = 0; nt < 4; nt++) {
            const int ch = wn * 8 + nt * 2 + (lane >> 4);
            const uint32_t baddr = brow + ((uint32_t)(ch ^ (bkk & 7)) << 4);
            uint32_t bh[4], bl[4];
            ldsm4t(bh, Bh + baddr);
            ldsm4t(bl, Bl + baddr);
            #pragma unroll
            for (int t = 0; t < 2; t++) {
                mma16816(acc[t][nt][0], ahf[t], bh[0], bh[1]);
                mma16816(acc[t][nt][1], ahf[t], bh[2], bh[3]);
                mma16816(acc[t][nt][0], ahf[t], bl[0], bl[1]);
                mma16816(acc[t][nt][1], ahf[t], bl[2], bl[3]);
                mma16816(acc[t][nt][0], alf[t], bh[0], bh[1]);
                mma16816(acc[t][nt][1], alf[t], bh[2], bh[3]);
            }
        }
        __syncthreads();
    }

    // ---- epilogue: +b1, ReLU, dot W2, reduce ----
    #pragma unroll
    for (int t = 0; t < 2; t++) {
        float plo = 0.f, phi = 0.f;
        #pragma unroll
        for (int nt = 0; nt < 4; nt++) {
            #pragma unroll
            for (int hh = 0; hh < 2; hh++) {
                int n0 = wn * 64 + nt * 16 + hh * 8 + (lane & 3) * 2;
                const float* cf = acc[t][nt][hh];
                float v0 = cf[0] + b1s[n0];
                float v1 = cf[1] + b1s[n0 + 1];
                float v2 = cf[2] + b1s[n0];
                float v3 = cf[3] + b1s[n0 + 1];
                v0 = v0 > 0.f ? v0 : 0.f;
                v1 = v1 > 0.f ? v1 : 0.f;
                v2 = v2 > 0.f ? v2 : 0.f;
                v3 = v3 > 0.f ? v3 : 0.f;
                plo += v0 * w2s[n0] + v1 * w2s[n0 + 1];
                phi += v2 * w2s[n0] + v3 * w2s[n0 + 1];
            }
        }
        plo += __shfl_xor_sync(0xFFFFFFFFu, plo, 1);
        plo += __shfl_xor_sync(0xFFFFFFFFu, plo, 2);
        phi += __shfl_xor_sync(0xFFFFFFFFu, phi, 1);
        phi += __shfl_xor_sync(0xFFFFFFFFu, phi, 2);
        if ((lane & 3) == 0) {
            int row = mg * 32 + t * 16 + (lane >> 2);
            red[wn * 64 + row]     = plo;
            red[wn * 64 + row + 8] = phi;
        }
    }
    __syncthreads();

    if (tid < BM) {
        int e = e0 + tid;
        if (e < E)
            out[e] = red[tid] + red[64 + tid] + red[128 + tid]
                   + red[192 + tid] + b2[0];
    }
}

extern "C" void kernel_launch(void* const* d_in, const int* in_sizes, int n_in,
                              void* d_out, int out_size)
{
    const float* h     = (const float*)d_in[0];
    const void*  edges = (const void*)d_in[1];
    const float* W1    = (const float*)d_in[2];
    const float* b1    = (const float*)d_in[3];
    const float* W2    = (const float*)d_in[4];
    const float* b2    = (const float*)d_in[5];
    float* out = (float*)d_out;

    int E = in_sizes[1] / 2;

    prep_w1<<<D, D>>>(W1);

    int grid = (E + BM - 1) / BM;
    cudaFuncSetAttribute(mlpdec_mma,
                         cudaFuncAttributeMaxDynamicSharedMemorySize,
                         SMEM_TOTAL);
    mlpdec_mma<<<grid, NT, SMEM_TOTAL>>>(h, edges, b1, W2, b2, out, E);
}

// round 17
// speedup vs baseline: 1.0015x; 1.0015x over previous
#include <cuda_runtime.h>
#include <cuda_fp16.h>
#include <cstdint>

#define D    256
#define BM   64            // edges per CTA
#define KC   16            // K chunk (one k-step per chunk)
#define NCHUNK 16
#define NT   256

// ---- smem byte offsets ----
#define AHI_OFF   0        // [64 rows][512B] swizzled fp16-hi   32KB
#define ALO_OFF   32768    // fp16-lo                            32KB
#define BBUF_OFF  65536    // 2 bufs x 16KB (hi 8KB + lo 8KB)    32KB
#define EIDX_OFF  98304    // 128 ints
#define B1S_OFF   (EIDX_OFF + 512)
#define W2S_OFF   (B1S_OFF + 1024)
#define RED_OFF   (W2S_OFF + 1024)   // 4 x 64 floats
#define SMEM_TOTAL (RED_OFF + 1024)  // 101888 B (~99.5KB) -> 2 CTAs/SM

// W1^T fp16 hi/lo, final swizzled tile layout, chunked by KC=16:
// chunk c: 16KB = [hi 8KB][lo 8KB]; within blob:
//   byte = kk*512 + ((nch ^ (kk&7))<<4) + (n&7)*2,  kk=k&15, nch=(n>>3)&31
__device__ __align__(16) char g_Bprep[262144];

__device__ __forceinline__ uint32_t smem_u32(const void* p) {
    uint32_t a;
    asm("{ .reg .u64 t; cvta.to.shared.u64 t, %1; cvt.u32.u64 %0, t; }"
        : "=r"(a) : "l"(p));
    return a;
}
__device__ __forceinline__ void cp16(uint32_t dst, const void* src) {
    asm volatile("{ .reg .u64 g; cvta.to.global.u64 g, %1;"
                 " cp.async.cg.shared.global [%0], [g], 16; }"
                 :: "r"(dst), "l"(src) : "memory");
}
__device__ __forceinline__ void ldsm4(uint32_t* r, uint32_t a) {
    asm volatile("ldmatrix.sync.aligned.m8n8.x4.shared.b16 {%0,%1,%2,%3}, [%4];"
                 : "=r"(r[0]), "=r"(r[1]), "=r"(r[2]), "=r"(r[3]) : "r"(a));
}
__device__ __forceinline__ void ldsm4t(uint32_t* r, uint32_t a) {
    asm volatile("ldmatrix.sync.aligned.m8n8.x4.trans.shared.b16 {%0,%1,%2,%3}, [%4];"
                 : "=r"(r[0]), "=r"(r[1]), "=r"(r[2]), "=r"(r[3]) : "r"(a));
}
__device__ __forceinline__ void mma16816(float* c, const uint32_t* a,
                                         uint32_t b0, uint32_t b1) {
    asm volatile("mma.sync.aligned.m16n8k16.row.col.f32.f16.f16.f32 "
                 "{%0,%1,%2,%3}, {%4,%5,%6,%7}, {%8,%9}, {%0,%1,%2,%3};"
                 : "+f"(c[0]), "+f"(c[1]), "+f"(c[2]), "+f"(c[3])
                 : "r"(a[0]), "r"(a[1]), "r"(a[2]), "r"(a[3]), "r"(b0), "r"(b1));
}

// ---- prep: W1 [k][n] f32 -> fp16 hi/lo, swizzled KC=16 tile blobs ----
__global__ void prep_w1(const float* __restrict__ W1) {
    int k = blockIdx.x;     // 0..255
    int n = threadIdx.x;    // 0..255
    float w = W1[k * D + n];
    __half hi = __float2half_rn(w);
    __half lo = __float2half_rn(w - __half2float(hi));
    int c = k >> 4, kk = k & 15;
    uint32_t base = (uint32_t)c * 16384u + (uint32_t)kk * 512u
                  + ((uint32_t)(((n >> 3) ^ (kk & 7)) & 31) << 4)
                  + (uint32_t)(n & 7) * 2u;
    *(__half*)(g_Bprep + base)        = hi;
    *(__half*)(g_Bprep + base + 8192) = lo;
}

__global__ __launch_bounds__(NT, 2)
void mlpdec_mma(const float* __restrict__ h,
                const void* __restrict__ edges_raw,
                const float* __restrict__ b1,
                const float* __restrict__ W2,
                const float* __restrict__ b2,
                float* __restrict__ out,
                int E)
{
    extern __shared__ char smem[];
    const uint32_t sb = smem_u32(smem);
    const int tid  = threadIdx.x;
    const int lane = tid & 31;
    const int wid  = tid >> 5;
    const int e0   = blockIdx.x * BM;

    int*   eidx = (int*)(smem + EIDX_OFF);
    float* b1s  = (float*)(smem + B1S_OFF);
    float* w2s  = (float*)(smem + W2S_OFF);
    float* red  = (float*)(smem + RED_OFF);

    // ---- kick off B chunk 0 copy immediately (16KB, 4x16B per thread) ----
    {
        const char* src = g_Bprep + tid * 16;
        uint32_t dst = sb + BBUF_OFF + tid * 16;
        #pragma unroll
        for (int i = 0; i < 4; i++) cp16(dst + i * 4096, src + i * 4096);
        asm volatile("cp.async.commit_group;" ::: "memory");
    }

    // ---- edge dtype probe (int64 of values <100000 has zero odd dwords) ----
    const int* w32 = (const int*)edges_raw;
    bool is64 = true;
    #pragma unroll
    for (int i = 0; i < 8; i++)
        if (w32[2 * i + 1] != 0) { is64 = false; break; }

    if (tid < BM) {
        long long e = (long long)e0 + tid;
        int s = 0, d = 0;
        if (e < E) {
            if (is64) {
                const long long* e64 = (const long long*)edges_raw;
                s = (int)e64[2 * e];
                d = (int)e64[2 * e + 1];
            } else {
                s = w32[2 * e];
                d = w32[2 * e + 1];
            }
        }
        eidx[tid]      = s;
        eidx[BM + tid] = d;
    }
    b1s[tid] = b1[tid];
    w2s[tid] = W2[tid];
    __syncthreads();

    // ---- produce A: hadamard -> fp16 hi/lo, swizzled ----
    {
        int row = tid & 63;
        int q   = tid >> 6;            // 0..3, covers k = q*64 .. q*64+63
        int s = eidx[row], d = eidx[BM + row];
        const float4* hs = (const float4*)(h + (size_t)s * D) + q * 16;
        const float4* hd = (const float4*)(h + (size_t)d * D) + q * 16;
        #pragma unroll
        for (int j = 0; j < 8; j++) {      // 8 chunks of 8 halfs
            float4 a0 = hs[2 * j], a1 = hs[2 * j + 1];
            float4 c0 = hd[2 * j], c1 = hd[2 * j + 1];
            float p[8] = { a0.x * c0.x, a0.y * c0.y, a0.z * c0.z, a0.w * c0.w,
                           a1.x * c1.x, a1.y * c1.y, a1.z * c1.z, a1.w * c1.w };
            union { __half hh[8]; uint4 v; } uhi, ulo;
            #pragma unroll
            for (int t = 0; t < 8; t++) {
                __half hv = __float2half_rn(p[t]);
                uhi.hh[t] = hv;
                ulo.hh[t] = __float2half_rn(p[t] - __half2float(hv));
            }
            int chunk = q * 8 + j;
            uint32_t byte = (uint32_t)row * 512u
                          + ((uint32_t)(chunk ^ (row & 7)) << 4);
            *(uint4*)(smem + AHI_OFF + byte) = uhi.v;
            *(uint4*)(smem + ALO_OFF + byte) = ulo.v;
        }
    }

    // ---- warp tiling: 2 M-groups (32 rows) x 4 N-groups (64 cols) ----
    const int mg = wid & 1;             // M group
    const int wn = wid >> 1;            // N group (0..3)
    float acc[2][4][2][4];              // [atile][ntile][nhalf][frag]
    #pragma unroll
    for (int t = 0; t < 2; t++)
        #pragma unroll
        for (int n = 0; n < 4; n++)
            #pragma unroll
            for (int hh = 0; hh < 2; hh++)
                #pragma unroll
                for (int f = 0; f < 4; f++) acc[t][n][hh][f] = 0.f;

    const uint32_t Ah = sb + AHI_OFF;
    const uint32_t Al = sb + ALO_OFF;
    const int arow0 = mg * 32 + (lane & 15);
    const int bkk   = (lane & 7) + ((lane >> 3) & 1) * 8;

    // ---- main loop: 16 K-chunks, double-buffered B via cp.async ----
    #pragma unroll 1
    for (int c = 0; c < NCHUNK; c++) {
        const int buf = c & 1;
        if (c < NCHUNK - 1) {
            const char* src = g_Bprep + (c + 1) * 16384 + tid * 16;
            uint32_t dst = sb + BBUF_OFF + ((c + 1) & 1) * 16384 + tid * 16;
            #pragma unroll
            for (int i = 0; i < 4; i++) cp16(dst + i * 4096, src + i * 4096);
            asm volatile("cp.async.commit_group;" ::: "memory");
            asm volatile("cp.async.wait_group 1;" ::: "memory");
        } else {
            asm volatile("cp.async.wait_group 0;" ::: "memory");
        }
        __syncthreads();

        // A fragments for this k-step (2 atiles, hi+lo)
        uint32_t ahf[2][4], alf[2][4];
        #pragma unroll
        for (int t = 0; t < 2; t++) {
            int arow = arow0 + t * 16;
            int achunk = c * 2 + (lane >> 4);
            uint32_t aaddr = (uint32_t)arow * 512u
                           + ((uint32_t)(achunk ^ (arow & 7)) << 4);
            ldsm4(ahf[t], Ah + aaddr);
            ldsm4(alf[t], Al + aaddr);
        }

        const uint32_t Bh = sb + BBUF_OFF + buf * 16384;
        const uint32_t Bl = Bh + 8192;
        const uint32_t brow = (uint32_t)bkk * 512u;

        #pragma unroll
        for (int nt = 0; nt < 4; nt++) {
            const int ch = wn * 8 + nt * 2 + (lane >> 4);
            const uint32_t baddr = brow + ((uint32_t)(ch ^ (bkk & 7)) << 4);
            uint32_t bh[4], bl[4];
            ldsm4t(bh, Bh + baddr);
            ldsm4t(bl, Bl + baddr);
            #pragma unroll
            for (int t = 0; t < 2; t++) {
                mma16816(acc[t][nt][0], ahf[t], bh[0], bh[1]);
                mma16816(acc[t][nt][1], ahf[t], bh[2], bh[3]);
                mma16816(acc[t][nt][0], ahf[t], bl[0], bl[1]);
                mma16816(acc[t][nt][1], ahf[t], bl[2], bl[3]);
                mma16816(acc[t][nt][0], alf[t], bh[0], bh[1]);
                mma16816(acc[t][nt][1], alf[t], bh[2], bh[3]);
            }
        }
        __syncthreads();
    }

    // ---- epilogue: +b1, ReLU, dot W2, reduce ----
    #pragma unroll
    for (int t = 0; t < 2; t++) {
        float plo = 0.f, phi = 0.f;
        #pragma unroll
        for (int nt = 0; nt < 4; nt++) {
            #pragma unroll
            for (int hh = 0; hh < 2; hh++) {
                int n0 = wn * 64 + nt * 16 + hh * 8 + (lane & 3) * 2;
                const float* cf = acc[t][nt][hh];
                float v0 = cf[0] + b1s[n0];
                float v1 = cf[1] + b1s[n0 + 1];
                float v2 = cf[2] + b1s[n0];
                float v3 = cf[3] + b1s[n0 + 1];
                v0 = v0 > 0.f ? v0 : 0.f;
                v1 = v1 > 0.f ? v1 : 0.f;
                v2 = v2 > 0.f ? v2 : 0.f;
                v3 = v3 > 0.f ? v3 : 0.f;
                plo += v0 * w2s[n0] + v1 * w2s[n0 + 1];
                phi += v2 * w2s[n0] + v3 * w2s[n0 + 1];
            }
        }
        plo += __shfl_xor_sync(0xFFFFFFFFu, plo, 1);
        plo += __shfl_xor_sync(0xFFFFFFFFu, plo, 2);
        phi += __shfl_xor_sync(0xFFFFFFFFu, phi, 1);
        phi += __shfl_xor_sync(0xFFFFFFFFu, phi, 2);
        if ((lane & 3) == 0) {
            int row = mg * 32 + t * 16 + (lane >> 2);
            red[wn * 64 + row]     = plo;
            red[wn * 64 + row + 8] = phi;
        }
    }
    __syncthreads();

    if (tid < BM) {
        int e = e0 + tid;
        if (e < E)
            out[e] = red[tid] + red[64 + tid] + red[128 + tid]
                   + red[192 + tid] + b2[0];
    }
}

extern "C" void kernel_launch(void* const* d_in, const int* in_sizes, int n_in,
                              void* d_out, int out_size)
{
    const float* h     = (const float*)d_in[0];
    const void*  edges = (const void*)d_in[1];
    const float* W1    = (const float*)d_in[2];
    const float* b1    = (const float*)d_in[3];
    const float* W2    = (const float*)d_in[4];
    const float* b2    = (const float*)d_in[5];
    float* out = (float*)d_out;

    int E = in_sizes[1] / 2;

    prep_w1<<<D, D>>>(W1);

    int grid = (E + BM - 1) / BM;
    cudaFuncSetAttribute(mlpdec_mma,
                         cudaFuncAttributeMaxDynamicSharedMemorySize,
                         SMEM_TOTAL);
    mlpdec_mma<<<grid, NT, SMEM_TOTAL>>>(h, edges, b1, W2, b2, out, E);
}